// round 7
// baseline (speedup 1.0000x reference)
#include <cuda_runtime.h>
#include <cuda_bf16.h>
#include <cub/block/block_radix_sort.cuh>
#include <cstdint>

#define B 64
#define N 4096
#define D 128
#define M 1024
#define L 128
#define NBUCKET 4096

// Scratch (device globals — no runtime allocation allowed)
__device__ float g_S[(size_t)B * L * N];          // 128 MB slices [B, L, N]
__device__ float g_A[L * N];                      // coefficient vectors
__device__ float g_C[L];                          // constants
__device__ __nv_bfloat16 g_Whi_sw[L * D];         // W hi split, pre-swizzled [l][k] image
__device__ __nv_bfloat16 g_Wlo_sw[L * D];         // W lo split, same layout

// ---------------------------------------------------------------------------
// helpers
// ---------------------------------------------------------------------------
__device__ __forceinline__ uint32_t smem_u32(const void* p) {
    uint32_t a;
    asm("{ .reg .u64 t; cvta.to.shared.u64 t, %1; cvt.u32.u64 %0, t; }" : "=r"(a) : "l"(p));
    return a;
}

// XOR swizzle for a [row][128 bf16] image (256B rows): 16B units XORed by row&7
__device__ __forceinline__ uint32_t swz(int row, int col) {
    return (uint32_t)(row * 256) + (((uint32_t)(col * 2)) ^ (uint32_t)((row & 7) << 4));
}

__device__ __forceinline__ void ldsm4(uint32_t* r, uint32_t addr) {
    asm volatile("ldmatrix.sync.aligned.m8n8.x4.shared.b16 {%0,%1,%2,%3}, [%4];"
                 : "=r"(r[0]), "=r"(r[1]), "=r"(r[2]), "=r"(r[3]) : "r"(addr));
}

__device__ __forceinline__ void mma16816(float* c, const uint32_t* a, const uint32_t* b) {
    asm volatile(
        "mma.sync.aligned.m16n8k16.row.col.f32.bf16.bf16.f32 "
        "{%0,%1,%2,%3}, {%4,%5,%6,%7}, {%8,%9}, {%0,%1,%2,%3};"
        : "+f"(c[0]), "+f"(c[1]), "+f"(c[2]), "+f"(c[3])
        : "r"(a[0]), "r"(a[1]), "r"(a[2]), "r"(a[3]), "r"(b[0]), "r"(b[1]));
}

// GEMM smem layout: Whi@0, Wlo@32K, Xhi@64K, Xlo@96K
#define GEMM_SMEM 131072

// Dummy no-op kernel: keeps the ncu -s window on sortdot (diagnostic; <1us).
__global__ void noop_kernel() {}

// ---------------------------------------------------------------------------
// Kernel A: per-l precompute. Normalize W -> bf16 hi/lo (pre-swizzled images),
// constant C, ref argsort folded with interp stencil into dense a[l, 0..N).
// ---------------------------------------------------------------------------
__global__ __launch_bounds__(256) void precompute_kernel(
    const float* __restrict__ theta_v,
    const float* __restrict__ ref,
    const float* __restrict__ weight)
{
    const int l = blockIdx.x;
    const int tid = threadIdx.x;

    typedef cub::BlockRadixSort<float, 256, 4, int> Sorter;
    __shared__ typename Sorter::TempStorage sort_tmp;
    __shared__ float red[8];
    __shared__ float w2_sh[M];

    // --- normalize theta row ---
    float tv = (tid < D) ? theta_v[l * D + tid] : 0.f;
    float ss = tv * tv;
    #pragma unroll
    for (int o = 16; o; o >>= 1) ss += __shfl_down_sync(0xffffffffu, ss, o);
    if ((tid & 31) == 0) red[tid >> 5] = ss;
    __syncthreads();
    if (tid == 0) {
        float s = 0.f;
        #pragma unroll
        for (int i = 0; i < 8; ++i) s += red[i];
        red[0] = s;
    }
    __syncthreads();
    {
        float nrm = sqrtf(red[0]);
        if (tid < D) {
            float wv = tv / nrm;
            __nv_bfloat16 h = __float2bfloat16(wv);
            __nv_bfloat16 lo = __float2bfloat16(wv - __bfloat162float(h));
            uint32_t sw = swz(l, tid);
            g_Whi_sw[sw >> 1] = h;
            g_Wlo_sw[sw >> 1] = lo;
        }
    }
    __syncthreads();  // red reused below

    // --- C[l] and sort keys ---
    float keys[4]; int vals[4];
    float cacc = 0.f;
    #pragma unroll
    for (int k = 0; k < 4; ++k) {
        int m = tid * 4 + k;
        float rv = ref[m * L + l];
        cacc += rv * weight[l * M + m];
        keys[k] = rv;
        vals[k] = m;
    }
    #pragma unroll
    for (int o = 16; o; o >>= 1) cacc += __shfl_down_sync(0xffffffffu, cacc, o);
    if ((tid & 31) == 0) red[tid >> 5] = cacc;
    __syncthreads();
    if (tid == 0) {
        float s = 0.f;
        #pragma unroll
        for (int i = 0; i < 8; ++i) s += red[i];
        g_C[l] = s;
    }
    __syncthreads();

    Sorter(sort_tmp).Sort(keys, vals);   // ascending, blocked arrangement
    __syncthreads();

    #pragma unroll
    for (int k = 0; k < 4; ++k) {
        int p = tid * 4 + k;
        w2_sh[vals[k]] = weight[l * M + p];
    }
    __syncthreads();

    float* Arow = g_A + l * N;
    for (int j = tid; j < N; j += 256) Arow[j] = 0.f;
    __syncthreads();

    for (int i = tid; i < M; i += 256) {
        long long num = (long long)(i + 1) * (N + 1);
        int q = (int)(num / (M + 1));
        int r = (int)(num - (long long)q * (M + 1));
        int j = q - 1;
        float tt = (float)((double)r * (1.0 / (double)(M + 1)));
        float w = w2_sh[i];
        Arow[j]     = (1.f - tt) * w;
        Arow[j + 1] = tt * w;
    }
}

// ---------------------------------------------------------------------------
// Kernel B (R4 config): mma.sync bf16 GEMM.  S[b,l,n] = sum_d X[b,n,d]*W[l,d]
// CTA = 128(l) x 128(n), K=128. 3-term bf16 split summed in fp32 accumulators:
//   S = Whi*Xhi + Whi*Xlo + Wlo*Xhi   (Wlo*Xlo dropped: ~2^-16 relative)
// 8 warps in 2(l) x 4(n) grid; warp tile 64 x 32 = 4 m-frags x 4 n-frags.
// ---------------------------------------------------------------------------
__global__ __launch_bounds__(256, 1) void gemm_mma_kernel(const float* __restrict__ X)
{
    extern __shared__ char smem[];
    const uint32_t sb = smem_u32(smem);
    const int tid = threadIdx.x;

    // --- copy pre-swizzled W images (32KB each) ---
    {
        const uint4* srch = reinterpret_cast<const uint4*>(g_Whi_sw);
        const uint4* srcl = reinterpret_cast<const uint4*>(g_Wlo_sw);
        uint4* dsth = reinterpret_cast<uint4*>(smem);
        uint4* dstl = reinterpret_cast<uint4*>(smem + 32768);
        #pragma unroll
        for (int i = 0; i < 8; ++i) {
            dsth[tid + i * 256] = srch[tid + i * 256];
            dstl[tid + i * 256] = srcl[tid + i * 256];
        }
    }

    // --- load X tile rows, split to bf16 hi/lo, store swizzled ---
    const size_t row0 = (size_t)blockIdx.x << 7;   // flattened (b*4096 + n) base
    {
        const int r  = tid >> 1;
        const int ch = (tid & 1) << 6;             // column half: 0 or 64
        const float4* xr = reinterpret_cast<const float4*>(X + (row0 + (size_t)r) * D + ch);
        char* xh = smem + 65536;
        char* xl = smem + 98304;
        const uint32_t rowbase = r * 256;
        const uint32_t xorv = (r & 7) << 4;
        #pragma unroll
        for (int i = 0; i < 16; ++i) {
            float4 v = xr[i];
            __nv_bfloat16 h0 = __float2bfloat16(v.x);
            __nv_bfloat16 h1 = __float2bfloat16(v.y);
            __nv_bfloat16 h2 = __float2bfloat16(v.z);
            __nv_bfloat16 h3 = __float2bfloat16(v.w);
            __nv_bfloat16 l0 = __float2bfloat16(v.x - __bfloat162float(h0));
            __nv_bfloat16 l1 = __float2bfloat16(v.y - __bfloat162float(h1));
            __nv_bfloat16 l2 = __float2bfloat16(v.z - __bfloat162float(h2));
            __nv_bfloat16 l3 = __float2bfloat16(v.w - __bfloat162float(h3));
            uint32_t ha = ((uint32_t)__bfloat16_as_ushort(h1) << 16) | __bfloat16_as_ushort(h0);
            uint32_t hb = ((uint32_t)__bfloat16_as_ushort(h3) << 16) | __bfloat16_as_ushort(h2);
            uint32_t la = ((uint32_t)__bfloat16_as_ushort(l1) << 16) | __bfloat16_as_ushort(l0);
            uint32_t lb = ((uint32_t)__bfloat16_as_ushort(l3) << 16) | __bfloat16_as_ushort(l2);
            int col = ch + i * 4;
            uint32_t off = rowbase + (((uint32_t)(col * 2)) ^ xorv);
            *reinterpret_cast<uint2*>(xh + off) = make_uint2(ha, hb);
            *reinterpret_cast<uint2*>(xl + off) = make_uint2(la, lb);
        }
    }
    __syncthreads();

    // --- warp MMA mainloop ---
    const int w = tid >> 5, lane = tid & 31;
    const int wl = w >> 2;          // 0..1 -> l offset wl*64
    const int wn = w & 3;           // 0..3 -> n offset wn*32
    const int laneRow = lane & 15;
    const int laneCol = (lane >> 4) << 3;

    float c[4][4][4];
    #pragma unroll
    for (int i = 0; i < 4; ++i)
        #pragma unroll
        for (int j = 0; j < 4; ++j)
            #pragma unroll
            for (int q = 0; q < 4; ++q) c[i][j][q] = 0.f;

    #pragma unroll 1
    for (int t = 0; t < 3; ++t) {
        const uint32_t Ab = sb + (t == 2 ? 32768u : 0u);
        const uint32_t Bb = sb + 65536u + (t == 1 ? 32768u : 0u);
        #pragma unroll 1
        for (int k8 = 0; k8 < 8; ++k8) {
            const int kk = k8 * 16;
            uint32_t a[4][4];
            #pragma unroll
            for (int mf = 0; mf < 4; ++mf) {
                int row = wl * 64 + mf * 16 + laneRow;
                int col = kk + laneCol;
                ldsm4(a[mf], Ab + swz(row, col));
            }
            uint32_t bfr[4][2];
            #pragma unroll
            for (int p = 0; p < 2; ++p) {
                int row = wn * 32 + p * 16 + laneRow;
                int col = kk + laneCol;
                uint32_t q[4];
                ldsm4(q, Bb + swz(row, col));
                bfr[2 * p][0] = q[0]; bfr[2 * p][1] = q[2];
                bfr[2 * p + 1][0] = q[1]; bfr[2 * p + 1][1] = q[3];
            }
            #pragma unroll
            for (int mf = 0; mf < 4; ++mf)
                #pragma unroll
                for (int nf = 0; nf < 4; ++nf)
                    mma16816(c[mf][nf], a[mf], bfr[nf]);
        }
    }

    // --- epilogue ---
    const int bb = (int)(row0 >> 12);
    const int n0 = (int)(row0 & (N - 1));
    const int rr = lane >> 2;
    const int cg = (lane & 3) << 1;
    #pragma unroll
    for (int mf = 0; mf < 4; ++mf) {
        const int l0 = wl * 64 + mf * 16 + rr;
        float* base0 = g_S + (((size_t)(bb * L + l0)) << 12);
        float* base1 = g_S + (((size_t)(bb * L + l0 + 8)) << 12);
        #pragma unroll
        for (int nf = 0; nf < 4; ++nf) {
            const int n = n0 + wn * 32 + nf * 8 + cg;
            *reinterpret_cast<float2*>(base0 + n) = make_float2(c[mf][nf][0], c[mf][nf][1]);
            *reinterpret_cast<float2*>(base1 + n) = make_float2(c[mf][nf][2], c[mf][nf][3]);
        }
    }
}

// ---------------------------------------------------------------------------
// Kernel C (v5): bucket-rank with thread-per-bucket finish.
// Phases: (1) bin + atomic hist (returns arrival index), (2) prefix sum,
// (3) scatter (plain store), (4) each thread sweeps strided buckets:
// read k values ONCE, sort in registers (8-wide network, INF-padded),
// acc += sum v_(j) * a[l, s+j] with a gathered from global (L1-hot, contiguous).
// Buckets with k>8 (rare Poisson tail) use the O(k^2) scan fallback.
// ---------------------------------------------------------------------------
#define SORT_SMEM ((N + NBUCKET) * 4)   // 32KB

#define CE(a, b) { float _mn = fminf(a, b), _mx = fmaxf(a, b); a = _mn; b = _mx; }

__global__ __launch_bounds__(512, 2) void sortdot_kernel(float* __restrict__ out)
{
    const int l = blockIdx.x >> 6;
    const int b = blockIdx.x & (B - 1);
    const int tid = threadIdx.x;
    const int lane = tid & 31;
    const int wid = tid >> 5;

    extern __shared__ char sds[];
    float* skey = reinterpret_cast<float*>(sds);          // N floats
    int*   hist = reinterpret_cast<int*>(skey + N);       // NBUCKET ints

    __shared__ float redf[16];
    __shared__ float redg[16];
    __shared__ int   reds[17];
    __shared__ float s_mn, s_scale;

    const float* row = g_S + (((size_t)(b * L + l)) << 12);
    float k[8];
    {
        float4 v0 = *reinterpret_cast<const float4*>(row + tid * 8);
        float4 v1 = *reinterpret_cast<const float4*>(row + tid * 8 + 4);
        k[0] = v0.x; k[1] = v0.y; k[2] = v0.z; k[3] = v0.w;
        k[4] = v1.x; k[5] = v1.y; k[6] = v1.z; k[7] = v1.w;
    }
    #pragma unroll
    for (int i = 0; i < NBUCKET / 512; ++i) hist[tid + i * 512] = 0;

    float mn = k[0], mx = k[0];
    #pragma unroll
    for (int i = 1; i < 8; ++i) { mn = fminf(mn, k[i]); mx = fmaxf(mx, k[i]); }
    #pragma unroll
    for (int o = 16; o; o >>= 1) {
        mn = fminf(mn, __shfl_xor_sync(0xffffffffu, mn, o));
        mx = fmaxf(mx, __shfl_xor_sync(0xffffffffu, mx, o));
    }
    if (lane == 0) { redf[wid] = mn; redg[wid] = mx; }
    __syncthreads();
    if (tid == 0) {
        float a = redf[0], c2 = redg[0];
        #pragma unroll
        for (int i = 1; i < 16; ++i) { a = fminf(a, redf[i]); c2 = fmaxf(c2, redg[i]); }
        s_mn = a;
        float range = c2 - a;
        s_scale = (range > 0.f) ? ((float)(NBUCKET - 1) / range) : 0.f;
    }
    __syncthreads();

    // --- (1) single atomic pass: histogram + arrival order ---
    const float mn0 = s_mn, scale = s_scale;
    int bk[8], qq[8];
    #pragma unroll
    for (int i = 0; i < 8; ++i) {
        int bb2 = (int)((k[i] - mn0) * scale);
        bk[i] = min(max(bb2, 0), NBUCKET - 1);
        qq[i] = atomicAdd(&hist[bk[i]], 1);
    }
    __syncthreads();

    // --- (2) exclusive prefix sum over NBUCKET bins (8 consecutive/thread) ---
    {
        int b0 = tid * 8;
        int h[8], s = 0;
        #pragma unroll
        for (int i = 0; i < 8; ++i) { h[i] = hist[b0 + i]; s += h[i]; }
        int inc = s;
        #pragma unroll
        for (int o = 1; o < 32; o <<= 1) {
            int t = __shfl_up_sync(0xffffffffu, inc, o);
            if (lane >= o) inc += t;
        }
        if (lane == 31) reds[wid + 1] = inc;
        __syncthreads();
        if (tid == 0) {
            reds[0] = 0;
            #pragma unroll
            for (int i = 1; i < 16; ++i) reds[i] += reds[i - 1];
        }
        __syncthreads();
        int base = inc - s + reds[wid];
        #pragma unroll
        for (int i = 0; i < 8; ++i) { hist[b0 + i] = base; base += h[i]; }
        __syncthreads();
    }

    // --- (3) scatter: position = start + arrival index (no atomics) ---
    #pragma unroll
    for (int i = 0; i < 8; ++i) {
        skey[hist[bk[i]] + qq[i]] = k[i];
    }
    __syncthreads();

    // --- (4) thread-per-bucket: sort k values in registers, dot with a ---
    const float* Arow = g_A + l * N;
    const float INF = __int_as_float(0x7f800000);
    float acc = 0.f;
    #pragma unroll 1
    for (int i = 0; i < 8; ++i) {
        const int bkt = tid + i * 512;              // strided for load balance
        const int s = hist[bkt];
        const int e = (bkt < NBUCKET - 1) ? hist[bkt + 1] : N;
        const int cnt = e - s;
        if (cnt <= 0) continue;
        if (cnt <= 8) {
            float v0 = skey[s];
            float v1 = (cnt > 1) ? skey[s + 1] : INF;
            float v2 = (cnt > 2) ? skey[s + 2] : INF;
            float v3 = (cnt > 3) ? skey[s + 3] : INF;
            float v4 = (cnt > 4) ? skey[s + 4] : INF;
            float v5 = (cnt > 5) ? skey[s + 5] : INF;
            float v6 = (cnt > 6) ? skey[s + 6] : INF;
            float v7 = (cnt > 7) ? skey[s + 7] : INF;
            // Batcher odd-even mergesort, 8 inputs, 19 CEs
            CE(v0, v1) CE(v2, v3) CE(v4, v5) CE(v6, v7)
            CE(v0, v2) CE(v1, v3) CE(v4, v6) CE(v5, v7)
            CE(v1, v2) CE(v5, v6)
            CE(v0, v4) CE(v1, v5) CE(v2, v6) CE(v3, v7)
            CE(v2, v4) CE(v3, v5)
            CE(v1, v2) CE(v3, v4) CE(v5, v6)
            acc += v0 * __ldg(Arow + s);
            if (cnt > 1) acc += v1 * __ldg(Arow + s + 1);
            if (cnt > 2) acc += v2 * __ldg(Arow + s + 2);
            if (cnt > 3) acc += v3 * __ldg(Arow + s + 3);
            if (cnt > 4) acc += v4 * __ldg(Arow + s + 4);
            if (cnt > 5) acc += v5 * __ldg(Arow + s + 5);
            if (cnt > 6) acc += v6 * __ldg(Arow + s + 6);
            if (cnt > 7) acc += v7 * __ldg(Arow + s + 7);
        } else {
            // rare oversized bucket: O(k^2) rank scan with index tiebreak
            for (int j = 0; j < cnt; ++j) {
                float v = skey[s + j];
                int r = s;
                for (int q = 0; q < cnt; ++q) {
                    float u = skey[s + q];
                    r += (u < v) || (u == v && q < j);
                }
                acc += v * __ldg(Arow + r);
            }
        }
    }

    #pragma unroll
    for (int o = 16; o; o >>= 1) acc += __shfl_down_sync(0xffffffffu, acc, o);
    if (lane == 0) redf[wid] = acc;
    __syncthreads();
    if (tid == 0) {
        float s = 0.f;
        #pragma unroll
        for (int i = 0; i < 16; ++i) s += redf[i];
        out[b * L + l] = g_C[l] - s;
    }
}

// ---------------------------------------------------------------------------
extern "C" void kernel_launch(void* const* d_in, const int* in_sizes, int n_in,
                              void* d_out, int out_size)
{
    const float* X       = (const float*)d_in[0];   // [B, N, D]
    const float* theta_v = (const float*)d_in[1];   // [L, D]
    const float* ref     = (const float*)d_in[2];   // [M, L]
    const float* weight  = (const float*)d_in[3];   // [L, M]
    float* out = (float*)d_out;                     // [B, L]

    static bool attr_set = false;
    if (!attr_set) {
        cudaFuncSetAttribute(gemm_mma_kernel,
                             cudaFuncAttributeMaxDynamicSharedMemorySize, GEMM_SMEM);
        cudaFuncSetAttribute(sortdot_kernel,
                             cudaFuncAttributeMaxDynamicSharedMemorySize, SORT_SMEM);
        attr_set = true;
    }

    noop_kernel<<<1, 32>>>();   // keep ncu -s window on sortdot (diagnostic)
    precompute_kernel<<<L, 256>>>(theta_v, ref, weight);
    gemm_mma_kernel<<<(B * N) / 128, 256, GEMM_SMEM>>>(X);
    sortdot_kernel<<<B * L, 512, SORT_SMEM>>>(out);
}

// round 8
// speedup vs baseline: 1.1018x; 1.1018x over previous
#include <cuda_runtime.h>
#include <cuda_bf16.h>
#include <cub/block/block_radix_sort.cuh>
#include <cstdint>

#define B 64
#define N 4096
#define D 128
#define M 1024
#define L 128
#define NBUCKET 4096

// Scratch (device globals — no runtime allocation allowed)
__device__ float g_S[(size_t)B * L * N];          // 128 MB slices [B, L, N]
__device__ float g_A[L * N];                      // coefficient vectors
__device__ float g_C[L];                          // constants
__device__ __nv_bfloat16 g_Whi_sw[L * D];         // W hi split, pre-swizzled [l][k] image
__device__ __nv_bfloat16 g_Wlo_sw[L * D];         // W lo split, same layout

// ---------------------------------------------------------------------------
// helpers
// ---------------------------------------------------------------------------
__device__ __forceinline__ uint32_t smem_u32(const void* p) {
    uint32_t a;
    asm("{ .reg .u64 t; cvta.to.shared.u64 t, %1; cvt.u32.u64 %0, t; }" : "=r"(a) : "l"(p));
    return a;
}

// XOR swizzle for a [row][128 bf16] image (256B rows): 16B units XORed by row&7
__device__ __forceinline__ uint32_t swz(int row, int col) {
    return (uint32_t)(row * 256) + (((uint32_t)(col * 2)) ^ (uint32_t)((row & 7) << 4));
}

__device__ __forceinline__ void ldsm4(uint32_t* r, uint32_t addr) {
    asm volatile("ldmatrix.sync.aligned.m8n8.x4.shared.b16 {%0,%1,%2,%3}, [%4];"
                 : "=r"(r[0]), "=r"(r[1]), "=r"(r[2]), "=r"(r[3]) : "r"(addr));
}

__device__ __forceinline__ void mma16816(float* c, const uint32_t* a, const uint32_t* b) {
    asm volatile(
        "mma.sync.aligned.m16n8k16.row.col.f32.bf16.bf16.f32 "
        "{%0,%1,%2,%3}, {%4,%5,%6,%7}, {%8,%9}, {%0,%1,%2,%3};"
        : "+f"(c[0]), "+f"(c[1]), "+f"(c[2]), "+f"(c[3])
        : "r"(a[0]), "r"(a[1]), "r"(a[2]), "r"(a[3]), "r"(b[0]), "r"(b[1]));
}

// GEMM smem layout: Whi@0, Wlo@32K, Xhi@64K, Xlo@96K
#define GEMM_SMEM 131072

// Dummy no-op kernel: keeps the ncu -s window on sortdot (diagnostic; <1us).
__global__ void noop_kernel() {}

// ---------------------------------------------------------------------------
// Kernel A: per-l precompute. Normalize W -> bf16 hi/lo (pre-swizzled images),
// constant C, ref argsort folded with interp stencil into dense a[l, 0..N).
// ---------------------------------------------------------------------------
__global__ __launch_bounds__(256) void precompute_kernel(
    const float* __restrict__ theta_v,
    const float* __restrict__ ref,
    const float* __restrict__ weight)
{
    const int l = blockIdx.x;
    const int tid = threadIdx.x;

    typedef cub::BlockRadixSort<float, 256, 4, int> Sorter;
    __shared__ typename Sorter::TempStorage sort_tmp;
    __shared__ float red[8];
    __shared__ float w2_sh[M];

    // --- normalize theta row ---
    float tv = (tid < D) ? theta_v[l * D + tid] : 0.f;
    float ss = tv * tv;
    #pragma unroll
    for (int o = 16; o; o >>= 1) ss += __shfl_down_sync(0xffffffffu, ss, o);
    if ((tid & 31) == 0) red[tid >> 5] = ss;
    __syncthreads();
    if (tid == 0) {
        float s = 0.f;
        #pragma unroll
        for (int i = 0; i < 8; ++i) s += red[i];
        red[0] = s;
    }
    __syncthreads();
    {
        float nrm = sqrtf(red[0]);
        if (tid < D) {
            float wv = tv / nrm;
            __nv_bfloat16 h = __float2bfloat16(wv);
            __nv_bfloat16 lo = __float2bfloat16(wv - __bfloat162float(h));
            uint32_t sw = swz(l, tid);
            g_Whi_sw[sw >> 1] = h;
            g_Wlo_sw[sw >> 1] = lo;
        }
    }
    __syncthreads();  // red reused below

    // --- C[l] and sort keys ---
    float keys[4]; int vals[4];
    float cacc = 0.f;
    #pragma unroll
    for (int k = 0; k < 4; ++k) {
        int m = tid * 4 + k;
        float rv = ref[m * L + l];
        cacc += rv * weight[l * M + m];
        keys[k] = rv;
        vals[k] = m;
    }
    #pragma unroll
    for (int o = 16; o; o >>= 1) cacc += __shfl_down_sync(0xffffffffu, cacc, o);
    if ((tid & 31) == 0) red[tid >> 5] = cacc;
    __syncthreads();
    if (tid == 0) {
        float s = 0.f;
        #pragma unroll
        for (int i = 0; i < 8; ++i) s += red[i];
        g_C[l] = s;
    }
    __syncthreads();

    Sorter(sort_tmp).Sort(keys, vals);   // ascending, blocked arrangement
    __syncthreads();

    #pragma unroll
    for (int k = 0; k < 4; ++k) {
        int p = tid * 4 + k;
        w2_sh[vals[k]] = weight[l * M + p];
    }
    __syncthreads();

    float* Arow = g_A + l * N;
    for (int j = tid; j < N; j += 256) Arow[j] = 0.f;
    __syncthreads();

    for (int i = tid; i < M; i += 256) {
        long long num = (long long)(i + 1) * (N + 1);
        int q = (int)(num / (M + 1));
        int r = (int)(num - (long long)q * (M + 1));
        int j = q - 1;
        float tt = (float)((double)r * (1.0 / (double)(M + 1)));
        float w = w2_sh[i];
        Arow[j]     = (1.f - tt) * w;
        Arow[j + 1] = tt * w;
    }
}

// ---------------------------------------------------------------------------
// Kernel B (R4 config): mma.sync bf16 GEMM.  S[b,l,n] = sum_d X[b,n,d]*W[l,d]
// CTA = 128(l) x 128(n), K=128. 3-term bf16 split summed in fp32 accumulators:
//   S = Whi*Xhi + Whi*Xlo + Wlo*Xhi   (Wlo*Xlo dropped: ~2^-16 relative)
// 8 warps in 2(l) x 4(n) grid; warp tile 64 x 32 = 4 m-frags x 4 n-frags.
// ---------------------------------------------------------------------------
__global__ __launch_bounds__(256, 1) void gemm_mma_kernel(const float* __restrict__ X)
{
    extern __shared__ char smem[];
    const uint32_t sb = smem_u32(smem);
    const int tid = threadIdx.x;

    // --- copy pre-swizzled W images (32KB each) ---
    {
        const uint4* srch = reinterpret_cast<const uint4*>(g_Whi_sw);
        const uint4* srcl = reinterpret_cast<const uint4*>(g_Wlo_sw);
        uint4* dsth = reinterpret_cast<uint4*>(smem);
        uint4* dstl = reinterpret_cast<uint4*>(smem + 32768);
        #pragma unroll
        for (int i = 0; i < 8; ++i) {
            dsth[tid + i * 256] = srch[tid + i * 256];
            dstl[tid + i * 256] = srcl[tid + i * 256];
        }
    }

    // --- load X tile rows, split to bf16 hi/lo, store swizzled ---
    const size_t row0 = (size_t)blockIdx.x << 7;   // flattened (b*4096 + n) base
    {
        const int r  = tid >> 1;
        const int ch = (tid & 1) << 6;             // column half: 0 or 64
        const float4* xr = reinterpret_cast<const float4*>(X + (row0 + (size_t)r) * D + ch);
        char* xh = smem + 65536;
        char* xl = smem + 98304;
        const uint32_t rowbase = r * 256;
        const uint32_t xorv = (r & 7) << 4;
        #pragma unroll
        for (int i = 0; i < 16; ++i) {
            float4 v = xr[i];
            __nv_bfloat16 h0 = __float2bfloat16(v.x);
            __nv_bfloat16 h1 = __float2bfloat16(v.y);
            __nv_bfloat16 h2 = __float2bfloat16(v.z);
            __nv_bfloat16 h3 = __float2bfloat16(v.w);
            __nv_bfloat16 l0 = __float2bfloat16(v.x - __bfloat162float(h0));
            __nv_bfloat16 l1 = __float2bfloat16(v.y - __bfloat162float(h1));
            __nv_bfloat16 l2 = __float2bfloat16(v.z - __bfloat162float(h2));
            __nv_bfloat16 l3 = __float2bfloat16(v.w - __bfloat162float(h3));
            uint32_t ha = ((uint32_t)__bfloat16_as_ushort(h1) << 16) | __bfloat16_as_ushort(h0);
            uint32_t hb = ((uint32_t)__bfloat16_as_ushort(h3) << 16) | __bfloat16_as_ushort(h2);
            uint32_t la = ((uint32_t)__bfloat16_as_ushort(l1) << 16) | __bfloat16_as_ushort(l0);
            uint32_t lb = ((uint32_t)__bfloat16_as_ushort(l3) << 16) | __bfloat16_as_ushort(l2);
            int col = ch + i * 4;
            uint32_t off = rowbase + (((uint32_t)(col * 2)) ^ xorv);
            *reinterpret_cast<uint2*>(xh + off) = make_uint2(ha, hb);
            *reinterpret_cast<uint2*>(xl + off) = make_uint2(la, lb);
        }
    }
    __syncthreads();

    // --- warp MMA mainloop ---
    const int w = tid >> 5, lane = tid & 31;
    const int wl = w >> 2;          // 0..1 -> l offset wl*64
    const int wn = w & 3;           // 0..3 -> n offset wn*32
    const int laneRow = lane & 15;
    const int laneCol = (lane >> 4) << 3;

    float c[4][4][4];
    #pragma unroll
    for (int i = 0; i < 4; ++i)
        #pragma unroll
        for (int j = 0; j < 4; ++j)
            #pragma unroll
            for (int q = 0; q < 4; ++q) c[i][j][q] = 0.f;

    #pragma unroll 1
    for (int t = 0; t < 3; ++t) {
        const uint32_t Ab = sb + (t == 2 ? 32768u : 0u);
        const uint32_t Bb = sb + 65536u + (t == 1 ? 32768u : 0u);
        #pragma unroll 1
        for (int k8 = 0; k8 < 8; ++k8) {
            const int kk = k8 * 16;
            uint32_t a[4][4];
            #pragma unroll
            for (int mf = 0; mf < 4; ++mf) {
                int row = wl * 64 + mf * 16 + laneRow;
                int col = kk + laneCol;
                ldsm4(a[mf], Ab + swz(row, col));
            }
            uint32_t bfr[4][2];
            #pragma unroll
            for (int p = 0; p < 2; ++p) {
                int row = wn * 32 + p * 16 + laneRow;
                int col = kk + laneCol;
                uint32_t q[4];
                ldsm4(q, Bb + swz(row, col));
                bfr[2 * p][0] = q[0]; bfr[2 * p][1] = q[2];
                bfr[2 * p + 1][0] = q[1]; bfr[2 * p + 1][1] = q[3];
            }
            #pragma unroll
            for (int mf = 0; mf < 4; ++mf)
                #pragma unroll
                for (int nf = 0; nf < 4; ++nf)
                    mma16816(c[mf][nf], a[mf], bfr[nf]);
        }
    }

    // --- epilogue ---
    const int bb = (int)(row0 >> 12);
    const int n0 = (int)(row0 & (N - 1));
    const int rr = lane >> 2;
    const int cg = (lane & 3) << 1;
    #pragma unroll
    for (int mf = 0; mf < 4; ++mf) {
        const int l0 = wl * 64 + mf * 16 + rr;
        float* base0 = g_S + (((size_t)(bb * L + l0)) << 12);
        float* base1 = g_S + (((size_t)(bb * L + l0 + 8)) << 12);
        #pragma unroll
        for (int nf = 0; nf < 4; ++nf) {
            const int n = n0 + wn * 32 + nf * 8 + cg;
            *reinterpret_cast<float2*>(base0 + n) = make_float2(c[mf][nf][0], c[mf][nf][1]);
            *reinterpret_cast<float2*>(base1 + n) = make_float2(c[mf][nf][2], c[mf][nf][3]);
        }
    }
}

// ---------------------------------------------------------------------------
// Kernel C (v6): R6 per-element rescan, tightened:
//  - hist packed as start | (cnt<<16) after prefix -> one LDS per rescan
//  - 16-lane shfl scans/reductions replace tid==0 serial loops
//  - hist zeroed with int4 stores
// ---------------------------------------------------------------------------
#define SORT_SMEM ((N + N + NBUCKET) * 4)   // 48KB

__global__ __launch_bounds__(512, 2) void sortdot_kernel(float* __restrict__ out)
{
    const int l = blockIdx.x >> 6;
    const int b = blockIdx.x & (B - 1);
    const int tid = threadIdx.x;
    const int lane = tid & 31;
    const int wid = tid >> 5;

    extern __shared__ char sds[];
    float* Asm  = reinterpret_cast<float*>(sds);          // N floats
    float* skey = Asm + N;                                // N floats
    int*   hist = reinterpret_cast<int*>(skey + N);       // NBUCKET ints

    __shared__ float redf[16];
    __shared__ float redg[16];
    __shared__ int   reds[16];
    __shared__ float s_mn, s_scale;

    const float* row = g_S + (((size_t)(b * L + l)) << 12);
    float k[8];
    {
        float4 v0 = *reinterpret_cast<const float4*>(row + tid * 8);
        float4 v1 = *reinterpret_cast<const float4*>(row + tid * 8 + 4);
        k[0] = v0.x; k[1] = v0.y; k[2] = v0.z; k[3] = v0.w;
        k[4] = v1.x; k[5] = v1.y; k[6] = v1.z; k[7] = v1.w;
    }
    {
        const float4* Ag = reinterpret_cast<const float4*>(g_A + l * N);
        *reinterpret_cast<float4*>(&Asm[tid * 8])     = Ag[tid * 2];
        *reinterpret_cast<float4*>(&Asm[tid * 8 + 4]) = Ag[tid * 2 + 1];
    }
    {   // zero histogram: 2 x int4 per thread
        int4* h4 = reinterpret_cast<int4*>(hist);
        h4[tid]       = make_int4(0, 0, 0, 0);
        h4[tid + 512] = make_int4(0, 0, 0, 0);
    }

    // --- block min/max (warp shfl + 16-lane combine) ---
    float mn = k[0], mx = k[0];
    #pragma unroll
    for (int i = 1; i < 8; ++i) { mn = fminf(mn, k[i]); mx = fmaxf(mx, k[i]); }
    #pragma unroll
    for (int o = 16; o; o >>= 1) {
        mn = fminf(mn, __shfl_xor_sync(0xffffffffu, mn, o));
        mx = fmaxf(mx, __shfl_xor_sync(0xffffffffu, mx, o));
    }
    if (lane == 0) { redf[wid] = mn; redg[wid] = mx; }
    __syncthreads();
    if (tid < 16) {
        float a = redf[tid], c2 = redg[tid];
        #pragma unroll
        for (int o = 8; o; o >>= 1) {
            a  = fminf(a,  __shfl_xor_sync(0x0000ffffu, a,  o));
            c2 = fmaxf(c2, __shfl_xor_sync(0x0000ffffu, c2, o));
        }
        if (tid == 0) {
            s_mn = a;
            float range = c2 - a;
            s_scale = (range > 0.f) ? ((float)(NBUCKET - 1) / range) : 0.f;
        }
    }
    __syncthreads();

    // --- (1) single atomic pass: histogram + arrival order ---
    const float mn0 = s_mn, scale = s_scale;
    int bk[8], qq[8];
    #pragma unroll
    for (int i = 0; i < 8; ++i) {
        int bb2 = (int)((k[i] - mn0) * scale);
        bk[i] = min(max(bb2, 0), NBUCKET - 1);
        qq[i] = atomicAdd(&hist[bk[i]], 1);
    }
    __syncthreads();

    // --- (2) exclusive prefix sum; write back packed start | (cnt<<16) ---
    {
        int b0 = tid * 8;
        int h[8], s = 0;
        #pragma unroll
        for (int i = 0; i < 8; ++i) { h[i] = hist[b0 + i]; s += h[i]; }
        int inc = s;
        #pragma unroll
        for (int o = 1; o < 32; o <<= 1) {
            int t = __shfl_up_sync(0xffffffffu, inc, o);
            if (lane >= o) inc += t;
        }
        if (lane == 31) reds[wid] = inc;    // warp totals (inclusive)
        __syncthreads();
        if (tid < 16) {                      // 16-lane exclusive scan of warp totals
            int x = reds[tid];
            int y = x;
            #pragma unroll
            for (int o = 1; o < 16; o <<= 1) {
                int t = __shfl_up_sync(0x0000ffffu, y, o);
                if (tid >= o) y += t;
            }
            reds[tid] = y - x;               // exclusive
        }
        __syncthreads();
        int base = inc - s + reds[wid];
        #pragma unroll
        for (int i = 0; i < 8; ++i) {
            hist[b0 + i] = base | (h[i] << 16);
            base += h[i];
        }
        __syncthreads();
    }

    // --- (3) scatter: position = start + arrival index (no atomics) ---
    int pos[8];
    #pragma unroll
    for (int i = 0; i < 8; ++i) {
        pos[i] = (hist[bk[i]] & 0xFFFF) + qq[i];
        skey[pos[i]] = k[i];
    }
    __syncthreads();

    // --- (4) rank + fused dot: one packed LDS gives start+cnt ---
    float acc = 0.f;
    #pragma unroll
    for (int i = 0; i < 8; ++i) {
        const float v = k[i];
        const int p = pos[i];
        const int word = hist[bk[i]];
        const int start = word & 0xFFFF;
        const int end = start + (word >> 16);
        int r = start;
        for (int q = start; q < end; ++q) {
            float u = skey[q];
            r += (u < v) || (u == v && q < p);
        }
        acc += v * Asm[r];
    }

    #pragma unroll
    for (int o = 16; o; o >>= 1) acc += __shfl_down_sync(0xffffffffu, acc, o);
    if (lane == 0) redf[wid] = acc;
    __syncthreads();
    if (tid < 16) {
        float s = redf[tid];
        #pragma unroll
        for (int o = 8; o; o >>= 1) s += __shfl_xor_sync(0x0000ffffu, s, o);
        if (tid == 0) out[b * L + l] = g_C[l] - s;
    }
}

// ---------------------------------------------------------------------------
extern "C" void kernel_launch(void* const* d_in, const int* in_sizes, int n_in,
                              void* d_out, int out_size)
{
    const float* X       = (const float*)d_in[0];   // [B, N, D]
    const float* theta_v = (const float*)d_in[1];   // [L, D]
    const float* ref     = (const float*)d_in[2];   // [M, L]
    const float* weight  = (const float*)d_in[3];   // [L, M]
    float* out = (float*)d_out;                     // [B, L]

    static bool attr_set = false;
    if (!attr_set) {
        cudaFuncSetAttribute(gemm_mma_kernel,
                             cudaFuncAttributeMaxDynamicSharedMemorySize, GEMM_SMEM);
        cudaFuncSetAttribute(sortdot_kernel,
                             cudaFuncAttributeMaxDynamicSharedMemorySize, SORT_SMEM);
        attr_set = true;
    }

    noop_kernel<<<1, 32>>>();   // keep ncu -s window on sortdot (diagnostic)
    precompute_kernel<<<L, 256>>>(theta_v, ref, weight);
    gemm_mma_kernel<<<(B * N) / 128, 256, GEMM_SMEM>>>(X);
    sortdot_kernel<<<B * L, 512, SORT_SMEM>>>(out);
}

// round 9
// speedup vs baseline: 1.1482x; 1.0420x over previous
#include <cuda_runtime.h>
#include <cuda_bf16.h>
#include <cub/block/block_radix_sort.cuh>
#include <cstdint>

#define B 64
#define N 4096
#define D 128
#define M 1024
#define L 128
#define NBUCKET 4096

// Scratch (device globals — no runtime allocation allowed)
__device__ float g_S[(size_t)B * L * N];          // 128 MB slices [B, L, N]
__device__ float g_A[L * N];                      // coefficient vectors
__device__ float g_C[L];                          // constants
__device__ __nv_bfloat16 g_Whi_sw[L * D];         // W hi split, pre-swizzled [l][k] image
__device__ __nv_bfloat16 g_Wlo_sw[L * D];         // W lo split, same layout

// ---------------------------------------------------------------------------
// helpers
// ---------------------------------------------------------------------------
__device__ __forceinline__ uint32_t smem_u32(const void* p) {
    uint32_t a;
    asm("{ .reg .u64 t; cvta.to.shared.u64 t, %1; cvt.u32.u64 %0, t; }" : "=r"(a) : "l"(p));
    return a;
}

// XOR swizzle for a [row][128 bf16] image (256B rows): 16B units XORed by row&7
__device__ __forceinline__ uint32_t swz(int row, int col) {
    return (uint32_t)(row * 256) + (((uint32_t)(col * 2)) ^ (uint32_t)((row & 7) << 4));
}

__device__ __forceinline__ void ldsm4(uint32_t* r, uint32_t addr) {
    asm volatile("ldmatrix.sync.aligned.m8n8.x4.shared.b16 {%0,%1,%2,%3}, [%4];"
                 : "=r"(r[0]), "=r"(r[1]), "=r"(r[2]), "=r"(r[3]) : "r"(addr));
}

__device__ __forceinline__ void mma16816(float* c, const uint32_t* a, const uint32_t* b) {
    asm volatile(
        "mma.sync.aligned.m16n8k16.row.col.f32.bf16.bf16.f32 "
        "{%0,%1,%2,%3}, {%4,%5,%6,%7}, {%8,%9}, {%0,%1,%2,%3};"
        : "+f"(c[0]), "+f"(c[1]), "+f"(c[2]), "+f"(c[3])
        : "r"(a[0]), "r"(a[1]), "r"(a[2]), "r"(a[3]), "r"(b[0]), "r"(b[1]));
}

// GEMM smem: Whi@0(32K), Wlo@32K, Xhi@64K(16K), Xlo@80K(16K) = 96KB
#define GEMM_SMEM 98304

// Dummy no-op kernel: keeps the ncu -s window on sortdot (diagnostic; <1us).
__global__ void noop_kernel() {}

// ---------------------------------------------------------------------------
// Kernel A: per-l precompute. Normalize W -> bf16 hi/lo (pre-swizzled images),
// constant C, ref argsort folded with interp stencil into dense a[l, 0..N).
// ---------------------------------------------------------------------------
__global__ __launch_bounds__(256) void precompute_kernel(
    const float* __restrict__ theta_v,
    const float* __restrict__ ref,
    const float* __restrict__ weight)
{
    const int l = blockIdx.x;
    const int tid = threadIdx.x;

    typedef cub::BlockRadixSort<float, 256, 4, int> Sorter;
    __shared__ typename Sorter::TempStorage sort_tmp;
    __shared__ float red[8];
    __shared__ float w2_sh[M];

    // --- normalize theta row ---
    float tv = (tid < D) ? theta_v[l * D + tid] : 0.f;
    float ss = tv * tv;
    #pragma unroll
    for (int o = 16; o; o >>= 1) ss += __shfl_down_sync(0xffffffffu, ss, o);
    if ((tid & 31) == 0) red[tid >> 5] = ss;
    __syncthreads();
    if (tid == 0) {
        float s = 0.f;
        #pragma unroll
        for (int i = 0; i < 8; ++i) s += red[i];
        red[0] = s;
    }
    __syncthreads();
    {
        float nrm = sqrtf(red[0]);
        if (tid < D) {
            float wv = tv / nrm;
            __nv_bfloat16 h = __float2bfloat16(wv);
            __nv_bfloat16 lo = __float2bfloat16(wv - __bfloat162float(h));
            uint32_t sw = swz(l, tid);
            g_Whi_sw[sw >> 1] = h;
            g_Wlo_sw[sw >> 1] = lo;
        }
    }
    __syncthreads();  // red reused below

    // --- C[l] and sort keys ---
    float keys[4]; int vals[4];
    float cacc = 0.f;
    #pragma unroll
    for (int k = 0; k < 4; ++k) {
        int m = tid * 4 + k;
        float rv = ref[m * L + l];
        cacc += rv * weight[l * M + m];
        keys[k] = rv;
        vals[k] = m;
    }
    #pragma unroll
    for (int o = 16; o; o >>= 1) cacc += __shfl_down_sync(0xffffffffu, cacc, o);
    if ((tid & 31) == 0) red[tid >> 5] = cacc;
    __syncthreads();
    if (tid == 0) {
        float s = 0.f;
        #pragma unroll
        for (int i = 0; i < 8; ++i) s += red[i];
        g_C[l] = s;
    }
    __syncthreads();

    Sorter(sort_tmp).Sort(keys, vals);   // ascending, blocked arrangement
    __syncthreads();

    #pragma unroll
    for (int k = 0; k < 4; ++k) {
        int p = tid * 4 + k;
        w2_sh[vals[k]] = weight[l * M + p];
    }
    __syncthreads();

    float* Arow = g_A + l * N;
    for (int j = tid; j < N; j += 256) Arow[j] = 0.f;
    __syncthreads();

    for (int i = tid; i < M; i += 256) {
        long long num = (long long)(i + 1) * (N + 1);
        int q = (int)(num / (M + 1));
        int r = (int)(num - (long long)q * (M + 1));
        int j = q - 1;
        float tt = (float)((double)r * (1.0 / (double)(M + 1)));
        float w = w2_sh[i];
        Arow[j]     = (1.f - tt) * w;
        Arow[j + 1] = tt * w;
    }
}

// ---------------------------------------------------------------------------
// Kernel B (v5): mma.sync bf16 GEMM at 2 CTAs/SM.
// S[b,l,n] = sum_d X[b,n,d] * W[l,d]; 3-term bf16 split in fp32 accum:
//   S = Whi*Xhi + Whi*Xlo + Wlo*Xhi   (Wlo*Xlo dropped: ~2^-16 relative)
// CTA = 128(l) x 64(n), K=128 unchunked, 96KB smem -> 2 CTAs/SM.
// 8 warps in 4(l) x 2(n) grid; warp tile 32 x 32 = 2 m-frags x 4 n-frags.
// ---------------------------------------------------------------------------
__global__ __launch_bounds__(256, 2) void gemm_mma_kernel(const float* __restrict__ X)
{
    extern __shared__ char smem[];
    const uint32_t sb = smem_u32(smem);
    const int tid = threadIdx.x;

    // --- copy pre-swizzled W images (32KB each) ---
    {
        const uint4* srch = reinterpret_cast<const uint4*>(g_Whi_sw);
        const uint4* srcl = reinterpret_cast<const uint4*>(g_Wlo_sw);
        uint4* dsth = reinterpret_cast<uint4*>(smem);
        uint4* dstl = reinterpret_cast<uint4*>(smem + 32768);
        #pragma unroll
        for (int i = 0; i < 8; ++i) {
            dsth[tid + i * 256] = srch[tid + i * 256];
            dstl[tid + i * 256] = srcl[tid + i * 256];
        }
    }

    // --- load X tile (64 rows), split to bf16 hi/lo, store swizzled ---
    const size_t row0 = (size_t)blockIdx.x << 6;   // flattened (b*4096 + n) base
    {
        const int r  = tid >> 2;                   // row 0..63
        const int ch = (tid & 3) << 5;             // column quarter: 0/32/64/96
        const float4* xr = reinterpret_cast<const float4*>(X + (row0 + (size_t)r) * D + ch);
        char* xh = smem + 65536;
        char* xl = smem + 81920;
        const uint32_t rowbase = r * 256;
        const uint32_t xorv = (r & 7) << 4;
        #pragma unroll
        for (int i = 0; i < 8; ++i) {
            float4 v = xr[i];
            __nv_bfloat16 h0 = __float2bfloat16(v.x);
            __nv_bfloat16 h1 = __float2bfloat16(v.y);
            __nv_bfloat16 h2 = __float2bfloat16(v.z);
            __nv_bfloat16 h3 = __float2bfloat16(v.w);
            __nv_bfloat16 l0 = __float2bfloat16(v.x - __bfloat162float(h0));
            __nv_bfloat16 l1 = __float2bfloat16(v.y - __bfloat162float(h1));
            __nv_bfloat16 l2 = __float2bfloat16(v.z - __bfloat162float(h2));
            __nv_bfloat16 l3 = __float2bfloat16(v.w - __bfloat162float(h3));
            uint32_t ha = ((uint32_t)__bfloat16_as_ushort(h1) << 16) | __bfloat16_as_ushort(h0);
            uint32_t hb = ((uint32_t)__bfloat16_as_ushort(h3) << 16) | __bfloat16_as_ushort(h2);
            uint32_t la = ((uint32_t)__bfloat16_as_ushort(l1) << 16) | __bfloat16_as_ushort(l0);
            uint32_t lb = ((uint32_t)__bfloat16_as_ushort(l3) << 16) | __bfloat16_as_ushort(l2);
            int col = ch + i * 4;
            uint32_t off = rowbase + (((uint32_t)(col * 2)) ^ xorv);
            *reinterpret_cast<uint2*>(xh + off) = make_uint2(ha, hb);
            *reinterpret_cast<uint2*>(xl + off) = make_uint2(la, lb);
        }
    }
    __syncthreads();

    // --- warp MMA mainloop: 4(l) x 2(n) warps, warp tile 32x32 ---
    const int w = tid >> 5, lane = tid & 31;
    const int wl = w >> 1;          // 0..3 -> l offset wl*32
    const int wn = w & 1;           // 0..1 -> n offset wn*32
    const int laneRow = lane & 15;
    const int laneCol = (lane >> 4) << 3;

    float c[2][4][4];
    #pragma unroll
    for (int i = 0; i < 2; ++i)
        #pragma unroll
        for (int j = 0; j < 4; ++j)
            #pragma unroll
            for (int q = 0; q < 4; ++q) c[i][j][q] = 0.f;

    #pragma unroll 1
    for (int t = 0; t < 3; ++t) {
        const uint32_t Ab = sb + (t == 2 ? 32768u : 0u);
        const uint32_t Bb = sb + 65536u + (t == 1 ? 16384u : 0u);
        #pragma unroll 1
        for (int k8 = 0; k8 < 8; ++k8) {
            const int kk = k8 * 16;
            uint32_t a[2][4];
            #pragma unroll
            for (int mf = 0; mf < 2; ++mf) {
                int row = wl * 32 + mf * 16 + laneRow;
                ldsm4(a[mf], Ab + swz(row, kk + laneCol));
            }
            uint32_t bfr[4][2];
            #pragma unroll
            for (int p = 0; p < 2; ++p) {
                int row = wn * 32 + p * 16 + laneRow;
                uint32_t q[4];
                ldsm4(q, Bb + swz(row, kk + laneCol));
                bfr[2 * p][0] = q[0]; bfr[2 * p][1] = q[2];
                bfr[2 * p + 1][0] = q[1]; bfr[2 * p + 1][1] = q[3];
            }
            #pragma unroll
            for (int mf = 0; mf < 2; ++mf)
                #pragma unroll
                for (int nf = 0; nf < 4; ++nf)
                    mma16816(c[mf][nf], a[mf], bfr[nf]);
        }
    }

    // --- epilogue ---
    const int bb = (int)(row0 >> 12);
    const int n0 = (int)(row0 & (N - 1));
    const int rr = lane >> 2;
    const int cg = (lane & 3) << 1;
    #pragma unroll
    for (int mf = 0; mf < 2; ++mf) {
        const int l0 = wl * 32 + mf * 16 + rr;
        float* base0 = g_S + (((size_t)(bb * L + l0)) << 12);
        float* base1 = g_S + (((size_t)(bb * L + l0 + 8)) << 12);
        #pragma unroll
        for (int nf = 0; nf < 4; ++nf) {
            const int n = n0 + wn * 32 + nf * 8 + cg;
            *reinterpret_cast<float2*>(base0 + n) = make_float2(c[mf][nf][0], c[mf][nf][1]);
            *reinterpret_cast<float2*>(base1 + n) = make_float2(c[mf][nf][2], c[mf][nf][3]);
        }
    }
}

// ---------------------------------------------------------------------------
// Kernel C (v7): per-element rescan, further tightened:
//  - packed hist word kept in registers from scatter to rescan (one hist LDS)
//  - cnt==1 fast path: rank = start, no skey store/scan
// ---------------------------------------------------------------------------
#define SORT_SMEM ((N + N + NBUCKET) * 4)   // 48KB

__global__ __launch_bounds__(512, 2) void sortdot_kernel(float* __restrict__ out)
{
    const int l = blockIdx.x >> 6;
    const int b = blockIdx.x & (B - 1);
    const int tid = threadIdx.x;
    const int lane = tid & 31;
    const int wid = tid >> 5;

    extern __shared__ char sds[];
    float* Asm  = reinterpret_cast<float*>(sds);          // N floats
    float* skey = Asm + N;                                // N floats
    int*   hist = reinterpret_cast<int*>(skey + N);       // NBUCKET ints

    __shared__ float redf[16];
    __shared__ float redg[16];
    __shared__ int   reds[16];
    __shared__ float s_mn, s_scale;

    const float* row = g_S + (((size_t)(b * L + l)) << 12);
    float k[8];
    {
        float4 v0 = *reinterpret_cast<const float4*>(row + tid * 8);
        float4 v1 = *reinterpret_cast<const float4*>(row + tid * 8 + 4);
        k[0] = v0.x; k[1] = v0.y; k[2] = v0.z; k[3] = v0.w;
        k[4] = v1.x; k[5] = v1.y; k[6] = v1.z; k[7] = v1.w;
    }
    {
        const float4* Ag = reinterpret_cast<const float4*>(g_A + l * N);
        *reinterpret_cast<float4*>(&Asm[tid * 8])     = Ag[tid * 2];
        *reinterpret_cast<float4*>(&Asm[tid * 8 + 4]) = Ag[tid * 2 + 1];
    }
    {   // zero histogram: 2 x int4 per thread
        int4* h4 = reinterpret_cast<int4*>(hist);
        h4[tid]       = make_int4(0, 0, 0, 0);
        h4[tid + 512] = make_int4(0, 0, 0, 0);
    }

    // --- block min/max (warp shfl + 16-lane combine) ---
    float mn = k[0], mx = k[0];
    #pragma unroll
    for (int i = 1; i < 8; ++i) { mn = fminf(mn, k[i]); mx = fmaxf(mx, k[i]); }
    #pragma unroll
    for (int o = 16; o; o >>= 1) {
        mn = fminf(mn, __shfl_xor_sync(0xffffffffu, mn, o));
        mx = fmaxf(mx, __shfl_xor_sync(0xffffffffu, mx, o));
    }
    if (lane == 0) { redf[wid] = mn; redg[wid] = mx; }
    __syncthreads();
    if (tid < 16) {
        float a = redf[tid], c2 = redg[tid];
        #pragma unroll
        for (int o = 8; o; o >>= 1) {
            a  = fminf(a,  __shfl_xor_sync(0x0000ffffu, a,  o));
            c2 = fmaxf(c2, __shfl_xor_sync(0x0000ffffu, c2, o));
        }
        if (tid == 0) {
            s_mn = a;
            float range = c2 - a;
            s_scale = (range > 0.f) ? ((float)(NBUCKET - 1) / range) : 0.f;
        }
    }
    __syncthreads();

    // --- (1) single atomic pass: histogram + arrival order ---
    const float mn0 = s_mn, scale = s_scale;
    int bk[8], qq[8];
    #pragma unroll
    for (int i = 0; i < 8; ++i) {
        int bb2 = (int)((k[i] - mn0) * scale);
        bk[i] = min(max(bb2, 0), NBUCKET - 1);
        qq[i] = atomicAdd(&hist[bk[i]], 1);
    }
    __syncthreads();

    // --- (2) exclusive prefix sum; write back packed start | (cnt<<16) ---
    {
        int b0 = tid * 8;
        int h[8], s = 0;
        #pragma unroll
        for (int i = 0; i < 8; ++i) { h[i] = hist[b0 + i]; s += h[i]; }
        int inc = s;
        #pragma unroll
        for (int o = 1; o < 32; o <<= 1) {
            int t = __shfl_up_sync(0xffffffffu, inc, o);
            if (lane >= o) inc += t;
        }
        if (lane == 31) reds[wid] = inc;    // warp totals (inclusive)
        __syncthreads();
        if (tid < 16) {                      // 16-lane exclusive scan of warp totals
            int x = reds[tid];
            int y = x;
            #pragma unroll
            for (int o = 1; o < 16; o <<= 1) {
                int t = __shfl_up_sync(0x0000ffffu, y, o);
                if (tid >= o) y += t;
            }
            reds[tid] = y - x;               // exclusive
        }
        __syncthreads();
        int base = inc - s + reds[wid];
        #pragma unroll
        for (int i = 0; i < 8; ++i) {
            hist[b0 + i] = base | (h[i] << 16);
            base += h[i];
        }
        __syncthreads();
    }

    // --- (3) scatter; keep packed word in regs; cnt==1 skips the store ---
    int word[8], pos[8];
    #pragma unroll
    for (int i = 0; i < 8; ++i) {
        word[i] = hist[bk[i]];
        pos[i] = (word[i] & 0xFFFF) + qq[i];
        if ((word[i] >> 16) > 1) skey[pos[i]] = k[i];
    }
    __syncthreads();

    // --- (4) rank + fused dot (no second hist read; cnt==1 fast path) ---
    float acc = 0.f;
    #pragma unroll
    for (int i = 0; i < 8; ++i) {
        const float v = k[i];
        const int start = word[i] & 0xFFFF;
        const int cnt = word[i] >> 16;
        int r = start;
        if (cnt > 1) {
            const int p = pos[i];
            const int end = start + cnt;
            for (int q = start; q < end; ++q) {
                float u = skey[q];
                r += (u < v) || (u == v && q < p);
            }
        }
        acc += v * Asm[r];
    }

    #pragma unroll
    for (int o = 16; o; o >>= 1) acc += __shfl_down_sync(0xffffffffu, acc, o);
    if (lane == 0) redf[wid] = acc;
    __syncthreads();
    if (tid < 16) {
        float s = redf[tid];
        #pragma unroll
        for (int o = 8; o; o >>= 1) s += __shfl_xor_sync(0x0000ffffu, s, o);
        if (tid == 0) out[b * L + l] = g_C[l] - s;
    }
}

// ---------------------------------------------------------------------------
extern "C" void kernel_launch(void* const* d_in, const int* in_sizes, int n_in,
                              void* d_out, int out_size)
{
    const float* X       = (const float*)d_in[0];   // [B, N, D]
    const float* theta_v = (const float*)d_in[1];   // [L, D]
    const float* ref     = (const float*)d_in[2];   // [M, L]
    const float* weight  = (const float*)d_in[3];   // [L, M]
    float* out = (float*)d_out;                     // [B, L]

    static bool attr_set = false;
    if (!attr_set) {
        cudaFuncSetAttribute(gemm_mma_kernel,
                             cudaFuncAttributeMaxDynamicSharedMemorySize, GEMM_SMEM);
        cudaFuncSetAttribute(sortdot_kernel,
                             cudaFuncAttributeMaxDynamicSharedMemorySize, SORT_SMEM);
        attr_set = true;
    }

    noop_kernel<<<1, 32>>>();   // keep ncu -s window on sortdot (diagnostic)
    precompute_kernel<<<L, 256>>>(theta_v, ref, weight);
    gemm_mma_kernel<<<(B * N) / 64, 256, GEMM_SMEM>>>(X);
    sortdot_kernel<<<B * L, 512, SORT_SMEM>>>(out);
}

// round 10
// speedup vs baseline: 1.1833x; 1.0306x over previous
#include <cuda_runtime.h>
#include <cuda_bf16.h>
#include <cub/block/block_radix_sort.cuh>
#include <cstdint>

#define B 64
#define N 4096
#define D 128
#define M 1024
#define L 128
#define NBUCKET 4096

// Scratch (device globals — no runtime allocation allowed)
__device__ float g_S[(size_t)B * L * N];          // 128 MB slices [B, L, N]
__device__ float g_A[L * N];                      // coefficient vectors
__device__ float g_C[L];                          // constants
__device__ __nv_bfloat16 g_Whi_sw[L * D];         // W hi split, pre-swizzled [l][k] image
__device__ __nv_bfloat16 g_Wlo_sw[L * D];         // W lo split, same layout

// ---------------------------------------------------------------------------
// helpers
// ---------------------------------------------------------------------------
__device__ __forceinline__ uint32_t smem_u32(const void* p) {
    uint32_t a;
    asm("{ .reg .u64 t; cvta.to.shared.u64 t, %1; cvt.u32.u64 %0, t; }" : "=r"(a) : "l"(p));
    return a;
}

// XOR swizzle for a [row][128 bf16] image (256B rows): 16B units XORed by row&7
__device__ __forceinline__ uint32_t swz(int row, int col) {
    return (uint32_t)(row * 256) + (((uint32_t)(col * 2)) ^ (uint32_t)((row & 7) << 4));
}

__device__ __forceinline__ void ldsm4(uint32_t* r, uint32_t addr) {
    asm volatile("ldmatrix.sync.aligned.m8n8.x4.shared.b16 {%0,%1,%2,%3}, [%4];"
                 : "=r"(r[0]), "=r"(r[1]), "=r"(r[2]), "=r"(r[3]) : "r"(addr));
}

__device__ __forceinline__ void mma16816(float* c, const uint32_t* a, const uint32_t* b) {
    asm volatile(
        "mma.sync.aligned.m16n8k16.row.col.f32.bf16.bf16.f32 "
        "{%0,%1,%2,%3}, {%4,%5,%6,%7}, {%8,%9}, {%0,%1,%2,%3};"
        : "+f"(c[0]), "+f"(c[1]), "+f"(c[2]), "+f"(c[3])
        : "r"(a[0]), "r"(a[1]), "r"(a[2]), "r"(a[3]), "r"(b[0]), "r"(b[1]));
}

// GEMM smem: Whi@0(32K), Wlo@32K, Xhi@64K(16K), Xlo@80K(16K) = 96KB
#define GEMM_SMEM 98304

// Dummy no-op kernel: keeps the ncu -s window on sortdot (diagnostic; <1us).
__global__ void noop_kernel() {}

// ---------------------------------------------------------------------------
// Kernel A: per-l precompute. Normalize W -> bf16 hi/lo (pre-swizzled images),
// constant C, ref argsort folded with interp stencil into dense a[l, 0..N).
// ---------------------------------------------------------------------------
__global__ __launch_bounds__(256) void precompute_kernel(
    const float* __restrict__ theta_v,
    const float* __restrict__ ref,
    const float* __restrict__ weight)
{
    const int l = blockIdx.x;
    const int tid = threadIdx.x;

    typedef cub::BlockRadixSort<float, 256, 4, int> Sorter;
    __shared__ typename Sorter::TempStorage sort_tmp;
    __shared__ float red[8];
    __shared__ float w2_sh[M];

    // --- normalize theta row ---
    float tv = (tid < D) ? theta_v[l * D + tid] : 0.f;
    float ss = tv * tv;
    #pragma unroll
    for (int o = 16; o; o >>= 1) ss += __shfl_down_sync(0xffffffffu, ss, o);
    if ((tid & 31) == 0) red[tid >> 5] = ss;
    __syncthreads();
    if (tid == 0) {
        float s = 0.f;
        #pragma unroll
        for (int i = 0; i < 8; ++i) s += red[i];
        red[0] = s;
    }
    __syncthreads();
    {
        float nrm = sqrtf(red[0]);
        if (tid < D) {
            float wv = tv / nrm;
            __nv_bfloat16 h = __float2bfloat16(wv);
            __nv_bfloat16 lo = __float2bfloat16(wv - __bfloat162float(h));
            uint32_t sw = swz(l, tid);
            g_Whi_sw[sw >> 1] = h;
            g_Wlo_sw[sw >> 1] = lo;
        }
    }
    __syncthreads();  // red reused below

    // --- C[l] and sort keys ---
    float keys[4]; int vals[4];
    float cacc = 0.f;
    #pragma unroll
    for (int k = 0; k < 4; ++k) {
        int m = tid * 4 + k;
        float rv = ref[m * L + l];
        cacc += rv * weight[l * M + m];
        keys[k] = rv;
        vals[k] = m;
    }
    #pragma unroll
    for (int o = 16; o; o >>= 1) cacc += __shfl_down_sync(0xffffffffu, cacc, o);
    if ((tid & 31) == 0) red[tid >> 5] = cacc;
    __syncthreads();
    if (tid == 0) {
        float s = 0.f;
        #pragma unroll
        for (int i = 0; i < 8; ++i) s += red[i];
        g_C[l] = s;
    }
    __syncthreads();

    Sorter(sort_tmp).Sort(keys, vals);   // ascending, blocked arrangement
    __syncthreads();

    #pragma unroll
    for (int k = 0; k < 4; ++k) {
        int p = tid * 4 + k;
        w2_sh[vals[k]] = weight[l * M + p];
    }
    __syncthreads();

    float* Arow = g_A + l * N;
    for (int j = tid; j < N; j += 256) Arow[j] = 0.f;
    __syncthreads();

    for (int i = tid; i < M; i += 256) {
        long long num = (long long)(i + 1) * (N + 1);
        int q = (int)(num / (M + 1));
        int r = (int)(num - (long long)q * (M + 1));
        int j = q - 1;
        float tt = (float)((double)r * (1.0 / (double)(M + 1)));
        float w = w2_sh[i];
        Arow[j]     = (1.f - tt) * w;
        Arow[j + 1] = tt * w;
    }
}

// ---------------------------------------------------------------------------
// Kernel B (R9 config): mma.sync bf16 GEMM at 2 CTAs/SM.
// S[b,l,n] = sum_d X[b,n,d] * W[l,d]; 3-term bf16 split in fp32 accum:
//   S = Whi*Xhi + Whi*Xlo + Wlo*Xhi   (Wlo*Xlo dropped: ~2^-16 relative)
// CTA = 128(l) x 64(n), K=128 unchunked, 96KB smem -> 2 CTAs/SM.
// 8 warps in 4(l) x 2(n) grid; warp tile 32 x 32 = 2 m-frags x 4 n-frags.
// ---------------------------------------------------------------------------
__global__ __launch_bounds__(256, 2) void gemm_mma_kernel(const float* __restrict__ X)
{
    extern __shared__ char smem[];
    const uint32_t sb = smem_u32(smem);
    const int tid = threadIdx.x;

    // --- copy pre-swizzled W images (32KB each) ---
    {
        const uint4* srch = reinterpret_cast<const uint4*>(g_Whi_sw);
        const uint4* srcl = reinterpret_cast<const uint4*>(g_Wlo_sw);
        uint4* dsth = reinterpret_cast<uint4*>(smem);
        uint4* dstl = reinterpret_cast<uint4*>(smem + 32768);
        #pragma unroll
        for (int i = 0; i < 8; ++i) {
            dsth[tid + i * 256] = srch[tid + i * 256];
            dstl[tid + i * 256] = srcl[tid + i * 256];
        }
    }

    // --- load X tile (64 rows), split to bf16 hi/lo, store swizzled ---
    const size_t row0 = (size_t)blockIdx.x << 6;   // flattened (b*4096 + n) base
    {
        const int r  = tid >> 2;                   // row 0..63
        const int ch = (tid & 3) << 5;             // column quarter: 0/32/64/96
        const float4* xr = reinterpret_cast<const float4*>(X + (row0 + (size_t)r) * D + ch);
        char* xh = smem + 65536;
        char* xl = smem + 81920;
        const uint32_t rowbase = r * 256;
        const uint32_t xorv = (r & 7) << 4;
        #pragma unroll
        for (int i = 0; i < 8; ++i) {
            float4 v = xr[i];
            __nv_bfloat16 h0 = __float2bfloat16(v.x);
            __nv_bfloat16 h1 = __float2bfloat16(v.y);
            __nv_bfloat16 h2 = __float2bfloat16(v.z);
            __nv_bfloat16 h3 = __float2bfloat16(v.w);
            __nv_bfloat16 l0 = __float2bfloat16(v.x - __bfloat162float(h0));
            __nv_bfloat16 l1 = __float2bfloat16(v.y - __bfloat162float(h1));
            __nv_bfloat16 l2 = __float2bfloat16(v.z - __bfloat162float(h2));
            __nv_bfloat16 l3 = __float2bfloat16(v.w - __bfloat162float(h3));
            uint32_t ha = ((uint32_t)__bfloat16_as_ushort(h1) << 16) | __bfloat16_as_ushort(h0);
            uint32_t hb = ((uint32_t)__bfloat16_as_ushort(h3) << 16) | __bfloat16_as_ushort(h2);
            uint32_t la = ((uint32_t)__bfloat16_as_ushort(l1) << 16) | __bfloat16_as_ushort(l0);
            uint32_t lb = ((uint32_t)__bfloat16_as_ushort(l3) << 16) | __bfloat16_as_ushort(l2);
            int col = ch + i * 4;
            uint32_t off = rowbase + (((uint32_t)(col * 2)) ^ xorv);
            *reinterpret_cast<uint2*>(xh + off) = make_uint2(ha, hb);
            *reinterpret_cast<uint2*>(xl + off) = make_uint2(la, lb);
        }
    }
    __syncthreads();

    // --- warp MMA mainloop: 4(l) x 2(n) warps, warp tile 32x32 ---
    const int w = tid >> 5, lane = tid & 31;
    const int wl = w >> 1;          // 0..3 -> l offset wl*32
    const int wn = w & 1;           // 0..1 -> n offset wn*32
    const int laneRow = lane & 15;
    const int laneCol = (lane >> 4) << 3;

    float c[2][4][4];
    #pragma unroll
    for (int i = 0; i < 2; ++i)
        #pragma unroll
        for (int j = 0; j < 4; ++j)
            #pragma unroll
            for (int q = 0; q < 4; ++q) c[i][j][q] = 0.f;

    #pragma unroll 1
    for (int t = 0; t < 3; ++t) {
        const uint32_t Ab = sb + (t == 2 ? 32768u : 0u);
        const uint32_t Bb = sb + 65536u + (t == 1 ? 16384u : 0u);
        #pragma unroll 1
        for (int k8 = 0; k8 < 8; ++k8) {
            const int kk = k8 * 16;
            uint32_t a[2][4];
            #pragma unroll
            for (int mf = 0; mf < 2; ++mf) {
                int row = wl * 32 + mf * 16 + laneRow;
                ldsm4(a[mf], Ab + swz(row, kk + laneCol));
            }
            uint32_t bfr[4][2];
            #pragma unroll
            for (int p = 0; p < 2; ++p) {
                int row = wn * 32 + p * 16 + laneRow;
                uint32_t q[4];
                ldsm4(q, Bb + swz(row, kk + laneCol));
                bfr[2 * p][0] = q[0]; bfr[2 * p][1] = q[2];
                bfr[2 * p + 1][0] = q[1]; bfr[2 * p + 1][1] = q[3];
            }
            #pragma unroll
            for (int mf = 0; mf < 2; ++mf)
                #pragma unroll
                for (int nf = 0; nf < 4; ++nf)
                    mma16816(c[mf][nf], a[mf], bfr[nf]);
        }
    }

    // --- epilogue ---
    const int bb = (int)(row0 >> 12);
    const int n0 = (int)(row0 & (N - 1));
    const int rr = lane >> 2;
    const int cg = (lane & 3) << 1;
    #pragma unroll
    for (int mf = 0; mf < 2; ++mf) {
        const int l0 = wl * 32 + mf * 16 + rr;
        float* base0 = g_S + (((size_t)(bb * L + l0)) << 12);
        float* base1 = g_S + (((size_t)(bb * L + l0 + 8)) << 12);
        #pragma unroll
        for (int nf = 0; nf < 4; ++nf) {
            const int n = n0 + wn * 32 + nf * 8 + cg;
            *reinterpret_cast<float2*>(base0 + n) = make_float2(c[mf][nf][0], c[mf][nf][1]);
            *reinterpret_cast<float2*>(base1 + n) = make_float2(c[mf][nf][2], c[mf][nf][3]);
        }
    }
}

// ---------------------------------------------------------------------------
// Kernel C (v8): per-element rescan at 3 CTAs/SM.
// __launch_bounds__(512,3) caps regs at 42; live state across barriers pruned
// to k[8] + word[8] + qq[8] (pos/bk recomputed from word+qq in phase 4).
// ---------------------------------------------------------------------------
#define SORT_SMEM ((N + N + NBUCKET) * 4)   // 48KB

__global__ __launch_bounds__(512, 3) void sortdot_kernel(float* __restrict__ out)
{
    const int l = blockIdx.x >> 6;
    const int b = blockIdx.x & (B - 1);
    const int tid = threadIdx.x;
    const int lane = tid & 31;
    const int wid = tid >> 5;

    extern __shared__ char sds[];
    float* Asm  = reinterpret_cast<float*>(sds);          // N floats
    float* skey = Asm + N;                                // N floats
    int*   hist = reinterpret_cast<int*>(skey + N);       // NBUCKET ints

    __shared__ float redf[16];
    __shared__ float redg[16];
    __shared__ int   reds[16];
    __shared__ float s_mn, s_scale;

    const float* row = g_S + (((size_t)(b * L + l)) << 12);
    float k[8];
    {
        float4 v0 = *reinterpret_cast<const float4*>(row + tid * 8);
        float4 v1 = *reinterpret_cast<const float4*>(row + tid * 8 + 4);
        k[0] = v0.x; k[1] = v0.y; k[2] = v0.z; k[3] = v0.w;
        k[4] = v1.x; k[5] = v1.y; k[6] = v1.z; k[7] = v1.w;
    }
    {
        const float4* Ag = reinterpret_cast<const float4*>(g_A + l * N);
        *reinterpret_cast<float4*>(&Asm[tid * 8])     = Ag[tid * 2];
        *reinterpret_cast<float4*>(&Asm[tid * 8 + 4]) = Ag[tid * 2 + 1];
    }
    {   // zero histogram: 2 x int4 per thread
        int4* h4 = reinterpret_cast<int4*>(hist);
        h4[tid]       = make_int4(0, 0, 0, 0);
        h4[tid + 512] = make_int4(0, 0, 0, 0);
    }

    // --- block min/max (warp shfl + 16-lane combine) ---
    float mn = k[0], mx = k[0];
    #pragma unroll
    for (int i = 1; i < 8; ++i) { mn = fminf(mn, k[i]); mx = fmaxf(mx, k[i]); }
    #pragma unroll
    for (int o = 16; o; o >>= 1) {
        mn = fminf(mn, __shfl_xor_sync(0xffffffffu, mn, o));
        mx = fmaxf(mx, __shfl_xor_sync(0xffffffffu, mx, o));
    }
    if (lane == 0) { redf[wid] = mn; redg[wid] = mx; }
    __syncthreads();
    if (tid < 16) {
        float a = redf[tid], c2 = redg[tid];
        #pragma unroll
        for (int o = 8; o; o >>= 1) {
            a  = fminf(a,  __shfl_xor_sync(0x0000ffffu, a,  o));
            c2 = fmaxf(c2, __shfl_xor_sync(0x0000ffffu, c2, o));
        }
        if (tid == 0) {
            s_mn = a;
            float range = c2 - a;
            s_scale = (range > 0.f) ? ((float)(NBUCKET - 1) / range) : 0.f;
        }
    }
    __syncthreads();

    // --- (1) single atomic pass: histogram + arrival order ---
    const float mn0 = s_mn, scale = s_scale;
    int qq[8];
    int word[8];                      // holds bucket id now; packed word later
    #pragma unroll
    for (int i = 0; i < 8; ++i) {
        int bb2 = (int)((k[i] - mn0) * scale);
        word[i] = min(max(bb2, 0), NBUCKET - 1);
        qq[i] = atomicAdd(&hist[word[i]], 1);
    }
    __syncthreads();

    // --- (2) exclusive prefix sum; write back packed start | (cnt<<16) ---
    {
        int b0 = tid * 8;
        int h[8], s = 0;
        #pragma unroll
        for (int i = 0; i < 8; ++i) { h[i] = hist[b0 + i]; s += h[i]; }
        int inc = s;
        #pragma unroll
        for (int o = 1; o < 32; o <<= 1) {
            int t = __shfl_up_sync(0xffffffffu, inc, o);
            if (lane >= o) inc += t;
        }
        if (lane == 31) reds[wid] = inc;    // warp totals (inclusive)
        __syncthreads();
        if (tid < 16) {                      // 16-lane exclusive scan of warp totals
            int x = reds[tid];
            int y = x;
            #pragma unroll
            for (int o = 1; o < 16; o <<= 1) {
                int t = __shfl_up_sync(0x0000ffffu, y, o);
                if (tid >= o) y += t;
            }
            reds[tid] = y - x;               // exclusive
        }
        __syncthreads();
        int base = inc - s + reds[wid];
        #pragma unroll
        for (int i = 0; i < 8; ++i) {
            hist[b0 + i] = base | (h[i] << 16);
            base += h[i];
        }
        __syncthreads();
    }

    // --- (3) scatter; replace bucket id with packed word (bk dead after) ---
    #pragma unroll
    for (int i = 0; i < 8; ++i) {
        word[i] = hist[word[i]];
        if ((word[i] >> 16) > 1) skey[(word[i] & 0xFFFF) + qq[i]] = k[i];
    }
    __syncthreads();

    // --- (4) rank + fused dot (pos recomputed; cnt==1 fast path) ---
    float acc = 0.f;
    #pragma unroll
    for (int i = 0; i < 8; ++i) {
        const float v = k[i];
        const int start = word[i] & 0xFFFF;
        const int cnt = word[i] >> 16;
        int r = start;
        if (cnt > 1) {
            const int p = start + qq[i];
            const int end = start + cnt;
            for (int q = start; q < end; ++q) {
                float u = skey[q];
                r += (u < v) || (u == v && q < p);
            }
        }
        acc += v * Asm[r];
    }

    #pragma unroll
    for (int o = 16; o; o >>= 1) acc += __shfl_down_sync(0xffffffffu, acc, o);
    if (lane == 0) redf[wid] = acc;
    __syncthreads();
    if (tid < 16) {
        float s = redf[tid];
        #pragma unroll
        for (int o = 8; o; o >>= 1) s += __shfl_xor_sync(0x0000ffffu, s, o);
        if (tid == 0) out[b * L + l] = g_C[l] - s;
    }
}

// ---------------------------------------------------------------------------
extern "C" void kernel_launch(void* const* d_in, const int* in_sizes, int n_in,
                              void* d_out, int out_size)
{
    const float* X       = (const float*)d_in[0];   // [B, N, D]
    const float* theta_v = (const float*)d_in[1];   // [L, D]
    const float* ref     = (const float*)d_in[2];   // [M, L]
    const float* weight  = (const float*)d_in[3];   // [L, M]
    float* out = (float*)d_out;                     // [B, L]

    static bool attr_set = false;
    if (!attr_set) {
        cudaFuncSetAttribute(gemm_mma_kernel,
                             cudaFuncAttributeMaxDynamicSharedMemorySize, GEMM_SMEM);
        cudaFuncSetAttribute(sortdot_kernel,
                             cudaFuncAttributeMaxDynamicSharedMemorySize, SORT_SMEM);
        attr_set = true;
    }

    noop_kernel<<<1, 32>>>();   // keep ncu -s window on sortdot (diagnostic)
    precompute_kernel<<<L, 256>>>(theta_v, ref, weight);
    gemm_mma_kernel<<<(B * N) / 64, 256, GEMM_SMEM>>>(X);
    sortdot_kernel<<<B * L, 512, SORT_SMEM>>>(out);
}